// round 1
// baseline (speedup 1.0000x reference)
#include <cuda_runtime.h>
#include <math.h>

#define F   128
#define S   10
#define KC  16

#define MAXN 200000
#define MAXB 20000

// static scratch (allocation-free rule)
__device__ float g_pre[(size_t)MAXN * F];      // t_j * (q_j @ mask)
__device__ float g_ln[MAXN];                    // t_j . a_neigh
__device__ float g_comb[(size_t)MAXB * 2 * F];  // [self | neigh_agg]

// ---------------------------------------------------------------------------
// Kernel A: per-table-row precompute.  grid = ceil(N/128), block = 128
// cross(128x16) = T(128x128) @ C^T, then q, then m = q @ mask, pre = T*m
// ---------------------------------------------------------------------------
__global__ void precompute_kernel(const float* __restrict__ neigh_table,
                                  const float* __restrict__ center,
                                  const float* __restrict__ cluster_mask,
                                  const float* __restrict__ alpha,
                                  int N) {
    __shared__ float s_center[KC][F + 1];   // pad -> conflict-free row reads
    __shared__ float s_mask[KC * F];
    __shared__ float s_an[F];
    __shared__ float s_c2[KC];
    __shared__ float s_T[128][33];          // 32-col chunk of 128 rows, pad 33
    __shared__ float s_n2[128];
    __shared__ float s_q[128][20];          // pad 20 -> 16B aligned rows

    const int tid = threadIdx.x;
    const int i = tid >> 2;    // 0..31 : row group (4 rows)
    const int j = tid & 3;     // 0..3  : k group   (4 clusters)
    const int rowbase = blockIdx.x * 128;

    for (int e = tid; e < KC * F; e += 128) {
        s_center[e >> 7][e & (F - 1)] = center[e];
        s_mask[e] = cluster_mask[e];
    }
    if (tid < F) s_an[tid] = alpha[F + tid];
    __syncthreads();

    if (tid < KC) {
        float a = 0.f;
        #pragma unroll 8
        for (int f = 0; f < F; f++) { float c = s_center[tid][f]; a += c * c; }
        s_c2[tid] = a;
    }

    float acc[4][4];
    #pragma unroll
    for (int m = 0; m < 4; m++)
        #pragma unroll
        for (int n = 0; n < 4; n++) acc[m][n] = 0.f;
    float n2[4] = {0.f, 0.f, 0.f, 0.f};
    float ln[4] = {0.f, 0.f, 0.f, 0.f};

    for (int ch = 0; ch < 4; ch++) {
        __syncthreads();   // protect s_T reuse across chunks
        #pragma unroll
        for (int it = 0; it < 32; it++) {      // 128 rows x 32 cols, coalesced
            int e = it * 128 + tid;
            int r = e >> 5, c = e & 31;
            int row = rowbase + r;
            float v = 0.f;
            if (row < N) v = neigh_table[(size_t)row * F + ch * 32 + c];
            s_T[r][c] = v;
        }
        __syncthreads();
        #pragma unroll
        for (int fc = 0; fc < 32; fc++) {
            float x0 = s_T[i * 4 + 0][fc];
            float x1 = s_T[i * 4 + 1][fc];
            float x2 = s_T[i * 4 + 2][fc];
            float x3 = s_T[i * 4 + 3][fc];
            float c0 = s_center[j * 4 + 0][ch * 32 + fc];
            float c1 = s_center[j * 4 + 1][ch * 32 + fc];
            float c2v = s_center[j * 4 + 2][ch * 32 + fc];
            float c3 = s_center[j * 4 + 3][ch * 32 + fc];
            acc[0][0] += x0 * c0;  acc[0][1] += x0 * c1;  acc[0][2] += x0 * c2v;  acc[0][3] += x0 * c3;
            acc[1][0] += x1 * c0;  acc[1][1] += x1 * c1;  acc[1][2] += x1 * c2v;  acc[1][3] += x1 * c3;
            acc[2][0] += x2 * c0;  acc[2][1] += x2 * c1;  acc[2][2] += x2 * c2v;  acc[2][3] += x2 * c3;
            acc[3][0] += x3 * c0;  acc[3][1] += x3 * c1;  acc[3][2] += x3 * c2v;  acc[3][3] += x3 * c3;
            if (j == 0) {
                float av = s_an[ch * 32 + fc];
                n2[0] += x0 * x0;  ln[0] += x0 * av;
                n2[1] += x1 * x1;  ln[1] += x1 * av;
                n2[2] += x2 * x2;  ln[2] += x2 * av;
                n2[3] += x3 * x3;  ln[3] += x3 * av;
            }
        }
    }

    if (j == 0) {
        #pragma unroll
        for (int m = 0; m < 4; m++) {
            s_n2[i * 4 + m] = n2[m];
            int row = rowbase + i * 4 + m;
            if (row < N) g_ln[row] = ln[m];
        }
    }
    __syncthreads();

    #pragma unroll
    for (int m = 0; m < 4; m++)
        #pragma unroll
        for (int n = 0; n < 4; n++) {
            int r = i * 4 + m, k = j * 4 + n;
            float d = s_n2[r] - 2.f * acc[m][n] + s_c2[k] + 1.f;
            s_q[r][k] = 1.f / d;
        }
    __syncthreads();

    // m = q @ mask; pre = T * m.  thread tid owns output column f = tid.
    float mk[KC];
    #pragma unroll
    for (int k = 0; k < KC; k++) mk[k] = s_mask[k * F + tid];
    int rmax = N - rowbase; if (rmax > 128) rmax = 128;
    for (int r = 0; r < rmax; r++) {
        const float4* q4 = (const float4*)(&s_q[r][0]);
        float4 qa = q4[0], qb = q4[1], qc = q4[2], qd = q4[3];
        float mval = qa.x * mk[0]  + qa.y * mk[1]  + qa.z * mk[2]  + qa.w * mk[3]
                   + qb.x * mk[4]  + qb.y * mk[5]  + qb.z * mk[6]  + qb.w * mk[7]
                   + qc.x * mk[8]  + qc.y * mk[9]  + qc.z * mk[10] + qc.w * mk[11]
                   + qd.x * mk[12] + qd.y * mk[13] + qd.z * mk[14] + qd.w * mk[15];
        size_t gi = (size_t)(rowbase + r) * F + tid;
        g_pre[gi] = neigh_table[gi] * mval;
    }
}

// ---------------------------------------------------------------------------
// Kernel B: gather + attention.  grid = ceil(B/4), block = 128 (thread = f)
// ---------------------------------------------------------------------------
__global__ void gather_kernel(const int* __restrict__ nodes,
                              const int* __restrict__ neigh_idx,
                              const float* __restrict__ self_table,
                              const float* __restrict__ alpha,
                              int B) {
    __shared__ float s_red[4];
    const int tid = threadIdx.x;
    const float a_self = alpha[tid];

    for (int rr = 0; rr < 4; rr++) {
        int row = blockIdx.x * 4 + rr;
        if (row >= B) return;                       // uniform across block
        int node = nodes[row];
        float sf = self_table[(size_t)node * F + tid];

        float v = sf * a_self;
        #pragma unroll
        for (int o = 16; o; o >>= 1) v += __shfl_xor_sync(0xffffffffu, v, o);
        if ((tid & 31) == 0) s_red[tid >> 5] = v;
        __syncthreads();
        float lself = s_red[0] + s_red[1] + s_red[2] + s_red[3];

        int ji[S];
        float att[S];
        float asum = 0.f;
        #pragma unroll
        for (int s = 0; s < S; s++) {
            ji[s] = neigh_idx[row * S + s];
            float l = lself + g_ln[ji[s]];
            l = fmaxf(l, 0.f);
            att[s] = expf(l);
            asum += att[s];
        }
        float inv = 1.f / asum;
        float agg = 0.f;
        #pragma unroll
        for (int s = 0; s < S; s++)
            agg += (att[s] * inv) * g_pre[(size_t)ji[s] * F + tid];

        g_comb[(size_t)row * (2 * F) + tid]     = sf;
        g_comb[(size_t)row * (2 * F) + F + tid] = agg;
        __syncthreads();                            // s_red reuse
    }
}

// ---------------------------------------------------------------------------
// Kernel C: out = relu(comb @ W^T).  M=B, K=256, N=128.
// grid = ceil(B/64), block = 256, thread tile 8x4, BK=32
// ---------------------------------------------------------------------------
__global__ void gemm_kernel(const float* __restrict__ weight,
                            float* __restrict__ out, int B) {
    __shared__ float As[32][68];    // A^T tile, pad 68 (16B-aligned rows)
    __shared__ float Bs[32][132];   // W^T tile, pad 132

    const int tid = threadIdx.x;
    const int tx = tid & 31;        // output-col group (4 cols each)
    const int ty = tid >> 5;        // output-row group (8 rows each)
    const int m0 = blockIdx.x * 64;

    float acc[8][4];
    #pragma unroll
    for (int mm = 0; mm < 8; mm++)
        #pragma unroll
        for (int nn = 0; nn < 4; nn++) acc[mm][nn] = 0.f;

    for (int kc = 0; kc < 2 * F; kc += 32) {
        #pragma unroll
        for (int it = 0; it < 2; it++) {            // A: 64 x 32
            int e = it * 256 + tid;
            int m = e >> 3, k4 = e & 7;
            float4 v = make_float4(0.f, 0.f, 0.f, 0.f);
            if (m0 + m < B)
                v = *(const float4*)&g_comb[(size_t)(m0 + m) * 256 + kc + k4 * 4];
            As[k4 * 4 + 0][m] = v.x;  As[k4 * 4 + 1][m] = v.y;
            As[k4 * 4 + 2][m] = v.z;  As[k4 * 4 + 3][m] = v.w;
        }
        #pragma unroll
        for (int it = 0; it < 4; it++) {            // W: 128 x 32
            int e = it * 256 + tid;
            int r = e >> 3, k4 = e & 7;
            float4 v = *(const float4*)&weight[r * 256 + kc + k4 * 4];
            Bs[k4 * 4 + 0][r] = v.x;  Bs[k4 * 4 + 1][r] = v.y;
            Bs[k4 * 4 + 2][r] = v.z;  Bs[k4 * 4 + 3][r] = v.w;
        }
        __syncthreads();
        #pragma unroll
        for (int k = 0; k < 32; k++) {
            float4 a0 = *(const float4*)&As[k][ty * 8];
            float4 a1 = *(const float4*)&As[k][ty * 8 + 4];
            float4 b  = *(const float4*)&Bs[k][tx * 4];
            float am[8] = {a0.x, a0.y, a0.z, a0.w, a1.x, a1.y, a1.z, a1.w};
            float bn[4] = {b.x, b.y, b.z, b.w};
            #pragma unroll
            for (int mm = 0; mm < 8; mm++)
                #pragma unroll
                for (int nn = 0; nn < 4; nn++)
                    acc[mm][nn] += am[mm] * bn[nn];
        }
        __syncthreads();
    }

    #pragma unroll
    for (int mm = 0; mm < 8; mm++) {
        int m = m0 + ty * 8 + mm;
        if (m < B) {
            float4 o;
            o.x = fmaxf(acc[mm][0], 0.f);
            o.y = fmaxf(acc[mm][1], 0.f);
            o.z = fmaxf(acc[mm][2], 0.f);
            o.w = fmaxf(acc[mm][3], 0.f);
            *(float4*)&out[(size_t)m * F + tx * 4] = o;
        }
    }
}

// ---------------------------------------------------------------------------
extern "C" void kernel_launch(void* const* d_in, const int* in_sizes, int n_in,
                              void* d_out, int out_size) {
    const int*   nodes        = (const int*)d_in[0];
    const int*   neigh_idx    = (const int*)d_in[1];
    const float* self_table   = (const float*)d_in[2];
    const float* neigh_table  = (const float*)d_in[3];
    const float* center       = (const float*)d_in[4];
    const float* cluster_mask = (const float*)d_in[5];
    const float* weight       = (const float*)d_in[6];
    const float* alpha        = (const float*)d_in[7];
    float* out = (float*)d_out;

    int B = in_sizes[0];
    int N = in_sizes[3] / F;

    precompute_kernel<<<(N + 127) / 128, 128>>>(neigh_table, center, cluster_mask, alpha, N);
    gather_kernel<<<(B + 3) / 4, 128>>>(nodes, neigh_idx, self_table, alpha, B);
    gemm_kernel<<<(B + 63) / 64, 256>>>(weight, out, B);
}

// round 2
// speedup vs baseline: 1.1780x; 1.1780x over previous
#include <cuda_runtime.h>
#include <math.h>

#define F   128
#define S   10
#define KC  16

#define MAXN 200000
#define MAXB 20000

// static scratch (allocation-free rule)
__device__ float g_pre[(size_t)MAXN * F];      // t_j * (q_j @ mask)
__device__ float g_ln[MAXN];                    // t_j . a_neigh
__device__ float g_comb[(size_t)MAXB * 2 * F];  // [self | neigh_agg]

// ---------------------------------------------------------------------------
// Kernel A: per-table-row precompute.  grid = ceil(N/128), block = 256
// Whole 128x128 tile resident in smem (pad 132, float4 everywhere).
// Phases: load -> n2/ln/c2 -> cross GEMM (4rx2k/thread) -> q -> maskMM+write
// ---------------------------------------------------------------------------
#define TP 132   // padded row stride for s_T / s_C (multiple of 4, odd/32*4)

__global__ void precompute_kernel(const float* __restrict__ neigh_table,
                                  const float* __restrict__ center,
                                  const float* __restrict__ cluster_mask,
                                  const float* __restrict__ alpha,
                                  int N) {
    extern __shared__ float sm[];
    float* s_T  = sm;                      // [128][TP]
    float* s_C  = s_T + 128 * TP;          // [16][TP]
    float* s_M  = s_C + 16 * TP;           // [16][128]
    float* s_Q  = s_M + 16 * 128;          // [128][16]
    float* s_an = s_Q + 128 * 16;          // [128]
    float* s_n2 = s_an + 128;              // [128]
    float* s_c2 = s_n2 + 128;              // [16]

    const int tid = threadIdx.x;
    const int rowbase = blockIdx.x * 128;
    const int nrows = min(128, N - rowbase);

    // ---- load constants ----
    #pragma unroll
    for (int e = tid; e < 512; e += 256) {                 // center 16x128
        int k = e >> 5, c4 = e & 31;
        float4 v = ((const float4*)center)[e];
        *(float4*)&s_C[k * TP + c4 * 4] = v;
    }
    #pragma unroll
    for (int e = tid; e < 512; e += 256)                   // mask 16x128
        ((float4*)s_M)[e] = ((const float4*)cluster_mask)[e];
    if (tid < 32) ((float4*)s_an)[tid] = ((const float4*)(alpha + F))[tid];

    // ---- load T tile (coalesced LDG.128, zero-padded OOB rows) ----
    #pragma unroll
    for (int it = 0; it < 16; it++) {
        int e = it * 256 + tid;
        int r = e >> 5, c4 = e & 31;
        float4 v = make_float4(0.f, 0.f, 0.f, 0.f);
        if (r < nrows)
            v = *(const float4*)&neigh_table[(size_t)(rowbase + r) * F + c4 * 4];
        *(float4*)&s_T[r * TP + c4 * 4] = v;
    }
    __syncthreads();

    // ---- n2 / ln (threads 0..127: one row each) and c2 (threads 128..143) ----
    if (tid < 128) {
        float n2 = 0.f, ln = 0.f;
        const float4* rowp = (const float4*)&s_T[tid * TP];
        const float4* anp  = (const float4*)s_an;
        #pragma unroll
        for (int f4 = 0; f4 < 32; f4++) {
            float4 x = rowp[f4], a = anp[f4];
            n2 += x.x * x.x + x.y * x.y + x.z * x.z + x.w * x.w;
            ln += x.x * a.x + x.y * a.y + x.z * a.z + x.w * a.w;
        }
        s_n2[tid] = n2;
        if (tid < nrows) g_ln[rowbase + tid] = ln;
    } else if (tid < 144) {
        int k = tid - 128;
        float a = 0.f;
        const float4* cp = (const float4*)&s_C[k * TP];
        #pragma unroll
        for (int f4 = 0; f4 < 32; f4++) {
            float4 c = cp[f4];
            a += c.x * c.x + c.y * c.y + c.z * c.z + c.w * c.w;
        }
        s_c2[k] = a;
    }
    __syncthreads();

    // ---- cross GEMM: thread = (rowgrp 0..31) x (kgrp 0..7), 4 rows x 2 k ----
    {
        const int rowgrp = tid >> 3, kgrp = tid & 7;
        float a00 = 0.f, a01 = 0.f, a10 = 0.f, a11 = 0.f;
        float a20 = 0.f, a21 = 0.f, a30 = 0.f, a31 = 0.f;
        const float* Tb = &s_T[rowgrp * 4 * TP];
        const float* Cb = &s_C[kgrp * 2 * TP];
        #pragma unroll
        for (int f4 = 0; f4 < 32; f4++) {
            float4 x0 = *(const float4*)&Tb[f4 * 4];
            float4 x1 = *(const float4*)&Tb[TP + f4 * 4];
            float4 x2 = *(const float4*)&Tb[2 * TP + f4 * 4];
            float4 x3 = *(const float4*)&Tb[3 * TP + f4 * 4];
            float4 c0 = *(const float4*)&Cb[f4 * 4];
            float4 c1 = *(const float4*)&Cb[TP + f4 * 4];
            a00 += x0.x * c0.x + x0.y * c0.y + x0.z * c0.z + x0.w * c0.w;
            a01 += x0.x * c1.x + x0.y * c1.y + x0.z * c1.z + x0.w * c1.w;
            a10 += x1.x * c0.x + x1.y * c0.y + x1.z * c0.z + x1.w * c0.w;
            a11 += x1.x * c1.x + x1.y * c1.y + x1.z * c1.z + x1.w * c1.w;
            a20 += x2.x * c0.x + x2.y * c0.y + x2.z * c0.z + x2.w * c0.w;
            a21 += x2.x * c1.x + x2.y * c1.y + x2.z * c1.z + x2.w * c1.w;
            a30 += x3.x * c0.x + x3.y * c0.y + x3.z * c0.z + x3.w * c0.w;
            a31 += x3.x * c1.x + x3.y * c1.y + x3.z * c1.z + x3.w * c1.w;
        }
        const int r0 = rowgrp * 4, k0 = kgrp * 2;
        float c2a = s_c2[k0] + 1.f, c2b = s_c2[k0 + 1] + 1.f;
        s_Q[(r0 + 0) * 16 + k0]     = 1.f / (s_n2[r0 + 0] - 2.f * a00 + c2a);
        s_Q[(r0 + 0) * 16 + k0 + 1] = 1.f / (s_n2[r0 + 0] - 2.f * a01 + c2b);
        s_Q[(r0 + 1) * 16 + k0]     = 1.f / (s_n2[r0 + 1] - 2.f * a10 + c2a);
        s_Q[(r0 + 1) * 16 + k0 + 1] = 1.f / (s_n2[r0 + 1] - 2.f * a11 + c2b);
        s_Q[(r0 + 2) * 16 + k0]     = 1.f / (s_n2[r0 + 2] - 2.f * a20 + c2a);
        s_Q[(r0 + 2) * 16 + k0 + 1] = 1.f / (s_n2[r0 + 2] - 2.f * a21 + c2b);
        s_Q[(r0 + 3) * 16 + k0]     = 1.f / (s_n2[r0 + 3] - 2.f * a30 + c2a);
        s_Q[(r0 + 3) * 16 + k0 + 1] = 1.f / (s_n2[r0 + 3] - 2.f * a31 + c2b);
    }
    __syncthreads();

    // ---- mask-MM + elementwise write: thread owns column f, 64 rows ----
    {
        const int f  = tid & 127;
        const int rh = tid >> 7;               // 0 or 1
        float mk[KC];
        #pragma unroll
        for (int k = 0; k < KC; k++) mk[k] = s_M[k * 128 + f];
        const int r0 = rh * 64;
        #pragma unroll 4
        for (int r = r0; r < r0 + 64; r++) {
            int row = rowbase + r;
            if (row >= N) break;               // uniform across block half
            const float4* q4 = (const float4*)&s_Q[r * 16];
            float4 qa = q4[0], qb = q4[1], qc = q4[2], qd = q4[3];
            float mv = qa.x * mk[0]  + qa.y * mk[1]  + qa.z * mk[2]  + qa.w * mk[3]
                     + qb.x * mk[4]  + qb.y * mk[5]  + qb.z * mk[6]  + qb.w * mk[7]
                     + qc.x * mk[8]  + qc.y * mk[9]  + qc.z * mk[10] + qc.w * mk[11]
                     + qd.x * mk[12] + qd.y * mk[13] + qd.z * mk[14] + qd.w * mk[15];
            g_pre[(size_t)row * F + f] = s_T[r * TP + f] * mv;
        }
    }
}

#define PRE_SMEM ((128 * TP + 16 * TP + 16 * 128 + 128 * 16 + 128 + 128 + 32) * 4)

// ---------------------------------------------------------------------------
// Kernel B: gather + attention.  grid = ceil(B/4), block = 128 (thread = f)
// ---------------------------------------------------------------------------
__global__ void gather_kernel(const int* __restrict__ nodes,
                              const int* __restrict__ neigh_idx,
                              const float* __restrict__ self_table,
                              const float* __restrict__ alpha,
                              int B) {
    __shared__ float s_red[4];
    const int tid = threadIdx.x;
    const float a_self = alpha[tid];

    for (int rr = 0; rr < 4; rr++) {
        int row = blockIdx.x * 4 + rr;
        if (row >= B) return;                       // uniform across block
        int node = nodes[row];
        float sf = self_table[(size_t)node * F + tid];

        float v = sf * a_self;
        #pragma unroll
        for (int o = 16; o; o >>= 1) v += __shfl_xor_sync(0xffffffffu, v, o);
        if ((tid & 31) == 0) s_red[tid >> 5] = v;
        __syncthreads();
        float lself = s_red[0] + s_red[1] + s_red[2] + s_red[3];

        int ji[S];
        float att[S];
        float asum = 0.f;
        #pragma unroll
        for (int s = 0; s < S; s++) {
            ji[s] = neigh_idx[row * S + s];
            float l = lself + g_ln[ji[s]];
            l = fmaxf(l, 0.f);
            att[s] = expf(l);
            asum += att[s];
        }
        float inv = 1.f / asum;
        float agg = 0.f;
        #pragma unroll
        for (int s = 0; s < S; s++)
            agg += (att[s] * inv) * g_pre[(size_t)ji[s] * F + tid];

        g_comb[(size_t)row * (2 * F) + tid]     = sf;
        g_comb[(size_t)row * (2 * F) + F + tid] = agg;
        __syncthreads();                            // s_red reuse
    }
}

// ---------------------------------------------------------------------------
// Kernel C: out = relu(comb @ W^T).  M=B, K=256, N=128.
// grid = ceil(B/64), block = 256, thread tile 8x4, BK=32
// ---------------------------------------------------------------------------
__global__ void gemm_kernel(const float* __restrict__ weight,
                            float* __restrict__ out, int B) {
    __shared__ float As[32][68];    // A^T tile, pad 68 (16B-aligned rows)
    __shared__ float Bs[32][132];   // W^T tile, pad 132

    const int tid = threadIdx.x;
    const int tx = tid & 31;        // output-col group (4 cols each)
    const int ty = tid >> 5;        // output-row group (8 rows each)
    const int m0 = blockIdx.x * 64;

    float acc[8][4];
    #pragma unroll
    for (int mm = 0; mm < 8; mm++)
        #pragma unroll
        for (int nn = 0; nn < 4; nn++) acc[mm][nn] = 0.f;

    for (int kc = 0; kc < 2 * F; kc += 32) {
        #pragma unroll
        for (int it = 0; it < 2; it++) {            // A: 64 x 32
            int e = it * 256 + tid;
            int m = e >> 3, k4 = e & 7;
            float4 v = make_float4(0.f, 0.f, 0.f, 0.f);
            if (m0 + m < B)
                v = *(const float4*)&g_comb[(size_t)(m0 + m) * 256 + kc + k4 * 4];
            As[k4 * 4 + 0][m] = v.x;  As[k4 * 4 + 1][m] = v.y;
            As[k4 * 4 + 2][m] = v.z;  As[k4 * 4 + 3][m] = v.w;
        }
        #pragma unroll
        for (int it = 0; it < 4; it++) {            // W: 128 x 32
            int e = it * 256 + tid;
            int r = e >> 3, k4 = e & 7;
            float4 v = *(const float4*)&weight[r * 256 + kc + k4 * 4];
            Bs[k4 * 4 + 0][r] = v.x;  Bs[k4 * 4 + 1][r] = v.y;
            Bs[k4 * 4 + 2][r] = v.z;  Bs[k4 * 4 + 3][r] = v.w;
        }
        __syncthreads();
        #pragma unroll
        for (int k = 0; k < 32; k++) {
            float4 a0 = *(const float4*)&As[k][ty * 8];
            float4 a1 = *(const float4*)&As[k][ty * 8 + 4];
            float4 b  = *(const float4*)&Bs[k][tx * 4];
            float am[8] = {a0.x, a0.y, a0.z, a0.w, a1.x, a1.y, a1.z, a1.w};
            float bn[4] = {b.x, b.y, b.z, b.w};
            #pragma unroll
            for (int mm = 0; mm < 8; mm++)
                #pragma unroll
                for (int nn = 0; nn < 4; nn++)
                    acc[mm][nn] += am[mm] * bn[nn];
        }
        __syncthreads();
    }

    #pragma unroll
    for (int mm = 0; mm < 8; mm++) {
        int m = m0 + ty * 8 + mm;
        if (m < B) {
            float4 o;
            o.x = fmaxf(acc[mm][0], 0.f);
            o.y = fmaxf(acc[mm][1], 0.f);
            o.z = fmaxf(acc[mm][2], 0.f);
            o.w = fmaxf(acc[mm][3], 0.f);
            *(float4*)&out[(size_t)m * F + tx * 4] = o;
        }
    }
}

// ---------------------------------------------------------------------------
extern "C" void kernel_launch(void* const* d_in, const int* in_sizes, int n_in,
                              void* d_out, int out_size) {
    const int*   nodes        = (const int*)d_in[0];
    const int*   neigh_idx    = (const int*)d_in[1];
    const float* self_table   = (const float*)d_in[2];
    const float* neigh_table  = (const float*)d_in[3];
    const float* center       = (const float*)d_in[4];
    const float* cluster_mask = (const float*)d_in[5];
    const float* weight       = (const float*)d_in[6];
    const float* alpha        = (const float*)d_in[7];
    float* out = (float*)d_out;

    int B = in_sizes[0];
    int N = in_sizes[3] / F;

    static bool attr_set = false;
    if (!attr_set) {
        cudaFuncSetAttribute(precompute_kernel,
                             cudaFuncAttributeMaxDynamicSharedMemorySize, PRE_SMEM);
        attr_set = true;
    }

    precompute_kernel<<<(N + 127) / 128, 256, PRE_SMEM>>>(neigh_table, center, cluster_mask, alpha, N);
    gather_kernel<<<(B + 3) / 4, 128>>>(nodes, neigh_idx, self_table, alpha, B);
    gemm_kernel<<<(B + 63) / 64, 256>>>(weight, out, B);
}

// round 3
// speedup vs baseline: 1.4028x; 1.1909x over previous
#include <cuda_runtime.h>
#include <math.h>

#define F   128
#define S   10
#define KC  16

#define MAXN 200000
#define MAXB 20000
#define TP   132     // padded tile row stride (words)

typedef unsigned long long ull;

// static scratch (allocation-free rule)
__device__ float g_pre[(size_t)MAXN * F];   // t_j * (q_j @ mask)
__device__ float g_ln[MAXN];                // t_j . a_neigh

// ---- packed f32x2 helpers (PTX-only; ptxas won't auto-fuse) ----
__device__ __forceinline__ ull ffma2(ull a, ull b, ull c) {
    ull d; asm("fma.rn.f32x2 %0,%1,%2,%3;" : "=l"(d) : "l"(a), "l"(b), "l"(c)); return d;
}
__device__ __forceinline__ ull fmul2(ull a, ull b) {
    ull d; asm("mul.rn.f32x2 %0,%1,%2;" : "=l"(d) : "l"(a), "l"(b)); return d;
}
__device__ __forceinline__ ull fpack(float a, float b) {
    ull d; asm("mov.b64 %0,{%1,%2};" : "=l"(d) : "f"(a), "f"(b)); return d;
}
__device__ __forceinline__ float2 funpack(ull a) {
    float2 f; asm("mov.b64 {%0,%1},%2;" : "=f"(f.x), "=f"(f.y) : "l"(a)); return f;
}
__device__ __forceinline__ float fsum2(ull a) { float2 f = funpack(a); return f.x + f.y; }

// ---------------------------------------------------------------------------
// Kernel A: per-table-row precompute. grid = ceil(N/128), block = 128.
// Thread = (rowpair rp, half h). Rows r0=rp, r1=rp+64 held in registers
// per f-chunk; center/mask reads are warp-uniform smem broadcasts.
// ---------------------------------------------------------------------------
__global__ void __launch_bounds__(128, 2)
precompute_kernel(const float* __restrict__ neigh_table,
                  const float* __restrict__ center,
                  const float* __restrict__ cluster_mask,
                  const float* __restrict__ alpha,
                  int N) {
    extern __shared__ float sm[];
    float* s_T   = sm;                  // [128][TP]
    float* s_C   = s_T + 128 * TP;      // [16][128]
    float* s_M   = s_C + 2048;          // [16][128]
    float* s_an  = s_M + 2048;          // [128]
    float* s_c2  = s_an + 128;          // [16]
    float* s_red = s_c2 + 16;           // [128][19]

    const int tid = threadIdx.x;
    const int rowbase = blockIdx.x * 128;
    const int nrows = min(128, N - rowbase);

    #pragma unroll
    for (int e = tid; e < 512; e += 128) {
        ((float4*)s_C)[e] = ((const float4*)center)[e];
        ((float4*)s_M)[e] = ((const float4*)cluster_mask)[e];
    }
    if (tid < 32) ((float4*)s_an)[tid] = ((const float4*)alpha)[tid + 32];  // a_neigh

    #pragma unroll
    for (int it = 0; it < 32; it++) {           // coalesced tile load
        int e = it * 128 + tid;
        int r = e >> 5, c4 = e & 31;
        float4 v = make_float4(0.f, 0.f, 0.f, 0.f);
        if (r < nrows) v = *(const float4*)&neigh_table[(size_t)(rowbase + r) * F + c4 * 4];
        *(float4*)&s_T[r * TP + c4 * 4] = v;
    }
    __syncthreads();

    if (tid < KC) {                              // c2 (16 threads, cheap)
        float a = 0.f;
        #pragma unroll 8
        for (int f4 = 0; f4 < 32; f4++) {
            float4 c = *(const float4*)&s_C[tid * 128 + f4 * 4];
            a += c.x * c.x + c.y * c.y + c.z * c.z + c.w * c.w;
        }
        s_c2[tid] = a;
    }

    const int rp = tid & 63, h = tid >> 6;       // h uniform per warp
    const int r0 = rp, r1 = rp + 64;
    const int fb = h * 64;

    ull acc0[KC], acc1[KC];
    #pragma unroll
    for (int k = 0; k < KC; k++) { acc0[k] = 0ull; acc1[k] = 0ull; }
    ull n20 = 0ull, n21 = 0ull, ln0 = 0ull, ln1 = 0ull;

    #pragma unroll 1
    for (int ch = 0; ch < 4; ch++) {             // 4 chunks x 16 floats
        ulonglong2 x0[4], x1[4];
        #pragma unroll
        for (int j = 0; j < 4; j++) {
            x0[j] = *(const ulonglong2*)&s_T[r0 * TP + fb + ch * 16 + j * 4];
            x1[j] = *(const ulonglong2*)&s_T[r1 * TP + fb + ch * 16 + j * 4];
        }
        #pragma unroll
        for (int j = 0; j < 4; j++) {            // n2 / ln folded in
            ulonglong2 a = *(const ulonglong2*)&s_an[fb + ch * 16 + j * 4];
            n20 = ffma2(x0[j].x, x0[j].x, n20);  n20 = ffma2(x0[j].y, x0[j].y, n20);
            n21 = ffma2(x1[j].x, x1[j].x, n21);  n21 = ffma2(x1[j].y, x1[j].y, n21);
            ln0 = ffma2(x0[j].x, a.x, ln0);      ln0 = ffma2(x0[j].y, a.y, ln0);
            ln1 = ffma2(x1[j].x, a.x, ln1);      ln1 = ffma2(x1[j].y, a.y, ln1);
        }
        #pragma unroll
        for (int k = 0; k < KC; k++) {
            #pragma unroll
            for (int j = 0; j < 4; j++) {
                ulonglong2 c = *(const ulonglong2*)&s_C[k * 128 + fb + ch * 16 + j * 4];
                acc0[k] = ffma2(x0[j].x, c.x, acc0[k]);  acc0[k] = ffma2(x0[j].y, c.y, acc0[k]);
                acc1[k] = ffma2(x1[j].x, c.x, acc1[k]);  acc1[k] = ffma2(x1[j].y, c.y, acc1[k]);
            }
        }
    }

    if (h == 1) {                                // partial sums -> smem
        #pragma unroll
        for (int k = 0; k < KC; k++) {
            s_red[r0 * 19 + k] = fsum2(acc0[k]);
            s_red[r1 * 19 + k] = fsum2(acc1[k]);
        }
        s_red[r0 * 19 + 16] = fsum2(n20);  s_red[r0 * 19 + 17] = fsum2(ln0);
        s_red[r1 * 19 + 16] = fsum2(n21);  s_red[r1 * 19 + 17] = fsum2(ln1);
    }
    __syncthreads();
    if (h == 0) {                                // reduce, q, ln out
        float n2A = fsum2(n20) + s_red[r0 * 19 + 16];
        float lnA = fsum2(ln0) + s_red[r0 * 19 + 17];
        float n2B = fsum2(n21) + s_red[r1 * 19 + 16];
        float lnB = fsum2(ln1) + s_red[r1 * 19 + 17];
        if (r0 < nrows) g_ln[rowbase + r0] = lnA;
        if (r1 < nrows) g_ln[rowbase + r1] = lnB;
        #pragma unroll
        for (int k = 0; k < KC; k++) {
            float cA = fsum2(acc0[k]) + s_red[r0 * 19 + k];
            float cB = fsum2(acc1[k]) + s_red[r1 * 19 + k];
            float c2k = s_c2[k] + 1.f;
            s_red[r0 * 19 + k] = 1.f / (n2A - 2.f * cA + c2k);
            s_red[r1 * 19 + k] = 1.f / (n2B - 2.f * cB + c2k);
        }
    }
    __syncthreads();

    ull qq0[KC], qq1[KC];
    #pragma unroll
    for (int k = 0; k < KC; k++) {
        float qA = s_red[r0 * 19 + k], qB = s_red[r1 * 19 + k];
        qq0[k] = fpack(qA, qA);  qq1[k] = fpack(qB, qB);
    }

    #pragma unroll 1
    for (int ch = 0; ch < 4; ch++) {             // mask-MM + elementwise, in place
        ulonglong2 mv0[4], mv1[4];
        #pragma unroll
        for (int j = 0; j < 4; j++) { mv0[j].x = mv0[j].y = 0ull; mv1[j].x = mv1[j].y = 0ull; }
        #pragma unroll
        for (int k = 0; k < KC; k++) {
            #pragma unroll
            for (int j = 0; j < 4; j++) {
                ulonglong2 m = *(const ulonglong2*)&s_M[k * 128 + fb + ch * 16 + j * 4];
                mv0[j].x = ffma2(qq0[k], m.x, mv0[j].x);  mv0[j].y = ffma2(qq0[k], m.y, mv0[j].y);
                mv1[j].x = ffma2(qq1[k], m.x, mv1[j].x);  mv1[j].y = ffma2(qq1[k], m.y, mv1[j].y);
            }
        }
        #pragma unroll
        for (int j = 0; j < 4; j++) {
            ulonglong2 xa = *(const ulonglong2*)&s_T[r0 * TP + fb + ch * 16 + j * 4];
            ulonglong2 xb = *(const ulonglong2*)&s_T[r1 * TP + fb + ch * 16 + j * 4];
            ulonglong2 pa, pb;
            pa.x = fmul2(xa.x, mv0[j].x);  pa.y = fmul2(xa.y, mv0[j].y);
            pb.x = fmul2(xb.x, mv1[j].x);  pb.y = fmul2(xb.y, mv1[j].y);
            *(ulonglong2*)&s_T[r0 * TP + fb + ch * 16 + j * 4] = pa;
            *(ulonglong2*)&s_T[r1 * TP + fb + ch * 16 + j * 4] = pb;
        }
    }
    __syncthreads();

    #pragma unroll
    for (int it = 0; it < 32; it++) {            // coalesced store
        int e = it * 128 + tid;
        int r = e >> 5, c4 = e & 31;
        if (r < nrows)
            *(float4*)&g_pre[(size_t)(rowbase + r) * F + c4 * 4] = *(const float4*)&s_T[r * TP + c4 * 4];
    }
}

#define A_SMEM ((128 * TP + 2048 + 2048 + 128 + 16 + 128 * 19) * 4)

// ---------------------------------------------------------------------------
// Kernel B: fused gather+attention+GEMM. grid = ceil(B/64), block = 256.
// Phase 1: 4 threads/row build comb tile in smem. Phase 2: GEMM from smem.
// ---------------------------------------------------------------------------
__global__ void __launch_bounds__(256, 2)
fused_kernel(const int* __restrict__ nodes,
             const int* __restrict__ neigh_idx,
             const float* __restrict__ self_table,
             const float* __restrict__ alpha,
             const float* __restrict__ weight,
             float* __restrict__ out, int B) {
    extern __shared__ float sm[];
    float* s_comb  = sm;                 // [64][260]
    float* s_alpha = s_comb + 64 * 260;  // [128]
    float* sAs     = s_alpha + 128;      // [32][68]
    float* sBs     = sAs + 32 * 68;      // [32][132]

    const int tid = threadIdx.x;
    if (tid < 32) ((float4*)s_alpha)[tid] = ((const float4*)alpha)[tid];  // a_self
    __syncthreads();

    // ---- phase 1: gather + attention (all threads active; clamp row) ----
    {
        const int r = tid >> 2, qt = tid & 3;
        const int row = min(blockIdx.x * 64 + r, B - 1);
        const int node = nodes[row];
        const float4* sp = (const float4*)(self_table + (size_t)node * F + qt * 32);
        float4 sf[8];
        float lp = 0.f;
        #pragma unroll
        for (int j = 0; j < 8; j++) {
            sf[j] = sp[j];
            float4 av = *(const float4*)&s_alpha[qt * 32 + j * 4];
            lp += sf[j].x * av.x + sf[j].y * av.y + sf[j].z * av.z + sf[j].w * av.w;
        }
        lp += __shfl_xor_sync(0xffffffffu, lp, 1);
        lp += __shfl_xor_sync(0xffffffffu, lp, 2);

        int ji[S];
        float att[S], asum = 0.f;
        #pragma unroll
        for (int s = 0; s < S; s++) ji[s] = neigh_idx[row * S + s];
        #pragma unroll
        for (int s = 0; s < S; s++) {
            float l = fmaxf(lp + g_ln[ji[s]], 0.f);
            att[s] = __expf(l);
            asum += att[s];
        }
        const float inv = 1.f / asum;
        float4 agg[8];
        #pragma unroll
        for (int j = 0; j < 8; j++) agg[j] = make_float4(0.f, 0.f, 0.f, 0.f);
        #pragma unroll
        for (int s = 0; s < S; s++) {
            const float w = att[s] * inv;
            const float4* pp = (const float4*)(g_pre + (size_t)ji[s] * F + qt * 32);
            #pragma unroll
            for (int j = 0; j < 8; j++) {
                float4 v = pp[j];
                agg[j].x += w * v.x;  agg[j].y += w * v.y;
                agg[j].z += w * v.z;  agg[j].w += w * v.w;
            }
        }
        #pragma unroll
        for (int j = 0; j < 8; j++) {
            *(float4*)&s_comb[r * 260 + qt * 32 + j * 4]       = sf[j];
            *(float4*)&s_comb[r * 260 + 128 + qt * 32 + j * 4] = agg[j];
        }
    }
    __syncthreads();

    // ---- phase 2: out = relu(comb @ W^T), thread tile 8x4, f32x2 FMAs ----
    const int tx = tid & 31, ty = tid >> 5;
    const int m0 = blockIdx.x * 64;
    ull acc2[8][2];
    #pragma unroll
    for (int mm = 0; mm < 8; mm++) { acc2[mm][0] = 0ull; acc2[mm][1] = 0ull; }

    #pragma unroll 1
    for (int kc = 0; kc < 2 * F; kc += 32) {
        #pragma unroll
        for (int it = 0; it < 2; it++) {         // A: 64x32 from s_comb (transpose)
            int e = it * 256 + tid;
            int m = e >> 3, k4 = e & 7;
            float4 v = *(const float4*)&s_comb[m * 260 + kc + k4 * 4];
            sAs[(k4 * 4 + 0) * 68 + m] = v.x;  sAs[(k4 * 4 + 1) * 68 + m] = v.y;
            sAs[(k4 * 4 + 2) * 68 + m] = v.z;  sAs[(k4 * 4 + 3) * 68 + m] = v.w;
        }
        #pragma unroll
        for (int it = 0; it < 4; it++) {         // W: 128x32 (transpose)
            int e = it * 256 + tid;
            int rr = e >> 3, k4 = e & 7;
            float4 v = *(const float4*)&weight[rr * 256 + kc + k4 * 4];
            sBs[(k4 * 4 + 0) * 132 + rr] = v.x;  sBs[(k4 * 4 + 1) * 132 + rr] = v.y;
            sBs[(k4 * 4 + 2) * 132 + rr] = v.z;  sBs[(k4 * 4 + 3) * 132 + rr] = v.w;
        }
        __syncthreads();
        #pragma unroll
        for (int k = 0; k < 32; k++) {
            float4 a0 = *(const float4*)&sAs[k * 68 + ty * 8];       // broadcast
            float4 a1 = *(const float4*)&sAs[k * 68 + ty * 8 + 4];   // broadcast
            ulonglong2 bv = *(const ulonglong2*)&sBs[k * 132 + tx * 4];
            float am[8] = {a0.x, a0.y, a0.z, a0.w, a1.x, a1.y, a1.z, a1.w};
            #pragma unroll
            for (int mm = 0; mm < 8; mm++) {
                ull ad = fpack(am[mm], am[mm]);
                acc2[mm][0] = ffma2(ad, bv.x, acc2[mm][0]);
                acc2[mm][1] = ffma2(ad, bv.y, acc2[mm][1]);
            }
        }
        __syncthreads();
    }

    #pragma unroll
    for (int mm = 0; mm < 8; mm++) {
        int m = m0 + ty * 8 + mm;
        if (m < B) {
            float2 p0 = funpack(acc2[mm][0]);
            float2 p1 = funpack(acc2[mm][1]);
            float4 o;
            o.x = fmaxf(p0.x, 0.f);  o.y = fmaxf(p0.y, 0.f);
            o.z = fmaxf(p1.x, 0.f);  o.w = fmaxf(p1.y, 0.f);
            *(float4*)&out[(size_t)m * F + tx * 4] = o;
        }
    }
}

#define B_SMEM ((64 * 260 + 128 + 32 * 68 + 32 * 132) * 4)

// ---------------------------------------------------------------------------
extern "C" void kernel_launch(void* const* d_in, const int* in_sizes, int n_in,
                              void* d_out, int out_size) {
    const int*   nodes        = (const int*)d_in[0];
    const int*   neigh_idx    = (const int*)d_in[1];
    const float* self_table   = (const float*)d_in[2];
    const float* neigh_table  = (const float*)d_in[3];
    const float* center       = (const float*)d_in[4];
    const float* cluster_mask = (const float*)d_in[5];
    const float* weight       = (const float*)d_in[6];
    const float* alpha        = (const float*)d_in[7];
    float* out = (float*)d_out;

    int B = in_sizes[0];
    int N = in_sizes[3] / F;

    cudaFuncSetAttribute(precompute_kernel, cudaFuncAttributeMaxDynamicSharedMemorySize, A_SMEM);
    cudaFuncSetAttribute(fused_kernel,      cudaFuncAttributeMaxDynamicSharedMemorySize, B_SMEM);

    precompute_kernel<<<(N + 127) / 128, 128, A_SMEM>>>(neigh_table, center, cluster_mask, alpha, N);
    fused_kernel<<<(B + 63) / 64, 256, B_SMEM>>>(nodes, neigh_idx, self_table, alpha, weight, out, B);
}